// round 1
// baseline (speedup 1.0000x reference)
#include <cuda_runtime.h>
#include <math.h>

#define Sq  2048
#define Dd  512
#define Hh  8
#define DHh 64
#define CWw 128
#define Ww  256   // 2*CW

// ---------------- scratch (device globals; no allocation in kernel_launch) ----
__device__ float g_cur[Sq * Dd];      // residual stream (4 MB)
__device__ float g_q[Sq * DHh];
__device__ float g_k[Sq * DHh];
__device__ float g_v[Sq * DHh];
__device__ float g_delta[Sq * DHh];
__device__ float g_y[Sq * Dd];        // pre-renorm y (4 MB)

// ---------------- init: cur = x ------------------------------------------------
__global__ void init_kernel(const float* __restrict__ x) {
    int i = blockIdx.x * blockDim.x + threadIdx.x;
    g_cur[i] = x[i];
}

// ---------------- shared GEMM body: 64x64 tile, BK=32, 4x4 microtile -----------
// C[m,n] = sum_k A[m,k]*B[n,k]  (+ Cadd[m,n] if given)
__device__ __forceinline__ void gemm_body(
    const float* __restrict__ A, int lda,
    const float* __restrict__ B, int ldb, int K,
    int m0, int n0,
    float* __restrict__ C, int ldc,
    const float* __restrict__ Cadd)
{
    __shared__ float Xs[64][36];   // [m][k], pad 4 keeps 16B alignment
    __shared__ float Ws[64][36];   // [n][k]
    const int t  = threadIdx.x;          // 256 threads
    const int tx = t & 15;               // 16 cols of 4
    const int ty = t >> 4;               // 16 rows of 4

    float acc[4][4] = {};

    for (int k0 = 0; k0 < K; k0 += 32) {
        #pragma unroll
        for (int r = 0; r < 2; r++) {
            int f  = t + r * 256;        // 512 float4 loads per operand tile
            int m  = f >> 3;
            int kv = f & 7;
            *(float4*)&Xs[m][kv * 4] =
                *(const float4*)&A[(size_t)(m0 + m) * lda + k0 + kv * 4];
            *(float4*)&Ws[m][kv * 4] =
                *(const float4*)&B[(size_t)(n0 + m) * ldb + k0 + kv * 4];
        }
        __syncthreads();

        #pragma unroll
        for (int k = 0; k < 32; k++) {
            float a[4], b[4];
            #pragma unroll
            for (int i = 0; i < 4; i++) a[i] = Xs[ty * 4 + i][k];
            #pragma unroll
            for (int j = 0; j < 4; j++) b[j] = Ws[tx * 4 + j][k];
            #pragma unroll
            for (int i = 0; i < 4; i++)
                #pragma unroll
                for (int j = 0; j < 4; j++)
                    acc[i][j] = fmaf(a[i], b[j], acc[i][j]);
        }
        __syncthreads();
    }

    #pragma unroll
    for (int i = 0; i < 4; i++) {
        int m = m0 + ty * 4 + i;
        #pragma unroll
        for (int j = 0; j < 4; j++) {
            int n = n0 + tx * 4 + j;
            float v = acc[i][j];
            if (Cadd) v += Cadd[(size_t)m * ldc + n];
            C[(size_t)m * ldc + n] = v;
        }
    }
}

// q/k/v = cur @ W^T   grid (S/64, 3)
__global__ void qkv_gemm(const float* __restrict__ Wq,
                         const float* __restrict__ Wk,
                         const float* __restrict__ Wvd, int h)
{
    int sel = blockIdx.y;
    const float* B = (sel == 0 ? Wq : sel == 1 ? Wk : Wvd) + (size_t)h * DHh * Dd;
    float* C = (sel == 0 ? g_q : sel == 1 ? g_k : g_v);
    gemm_body(g_cur, Dd, B, Dd, Dd, blockIdx.x * 64, 0, C, DHh, nullptr);
}

// y = cur + delta @ Wvu^T   grid (S/64, D/64)
__global__ void up_gemm(const float* __restrict__ Wvu, int h)
{
    gemm_body(g_delta, DHh, Wvu + (size_t)h * Dd * DHh, DHh, DHh,
              blockIdx.x * 64, blockIdx.y * 64, g_y, Dd, g_cur);
}

// ---------------- windowed attention: one block per token ----------------------
__global__ void attn_kernel()
{
    const int j = blockIdx.x;
    const int t = threadIdx.x;   // 256 threads, one per window slot
    __shared__ float qs[DHh];
    __shared__ float ws[Ww];
    __shared__ float red[8];
    __shared__ float part[4][DHh];

    if (t < DHh) qs[t] = g_q[j * DHh + t];
    __syncthreads();

    // score for window slot t  (key index j-128+t)
    const int iw = j - CWw + t;
    const bool valid = (iw >= 0) && (iw < Sq);
    float s = -INFINITY;
    if (valid) {
        const float4* kr = (const float4*)&g_k[(size_t)iw * DHh];
        const float4* qr = (const float4*)qs;
        float acc = 0.f;
        #pragma unroll
        for (int d = 0; d < DHh / 4; d++) {
            float4 kk = kr[d];
            float4 qq = qr[d];
            acc += kk.x * qq.x + kk.y * qq.y + kk.z * qq.z + kk.w * qq.w;
        }
        s = acc * 0.125f;   // 1/sqrt(64)
    }

    // block max
    float m = s;
    #pragma unroll
    for (int o = 16; o; o >>= 1) m = fmaxf(m, __shfl_xor_sync(0xffffffffu, m, o));
    if ((t & 31) == 0) red[t >> 5] = m;
    __syncthreads();
    m = red[0];
    #pragma unroll
    for (int w = 1; w < 8; w++) m = fmaxf(m, red[w]);
    __syncthreads();

    float e = valid ? __expf(s - m) : 0.f;

    // block sum
    float sm = e;
    #pragma unroll
    for (int o = 16; o; o >>= 1) sm += __shfl_xor_sync(0xffffffffu, sm, o);
    if ((t & 31) == 0) red[t >> 5] = sm;
    __syncthreads();
    float total = 0.f;
    #pragma unroll
    for (int w = 0; w < 8; w++) total += red[w];

    ws[t] = e / total;
    __syncthreads();

    // delta[d] = sum_w ws[w] * v[j-128+w][d]; 4 groups x 64 d
    const int g = t >> 6;
    const int d = t & 63;
    int wb = g * 64, we = g * 64 + 64;
    if (wb < CWw - j) wb = CWw - j;                 // w >= 128 - j
    int wmax = Sq + CWw - j;                        // w < S + 128 - j
    if (we > wmax) we = wmax;
    float acc = 0.f;
    for (int w = wb; w < we; w++)
        acc += ws[w] * g_v[(size_t)(j - CWw + w) * DHh + d];
    part[g][d] = acc;
    __syncthreads();

    if (t < DHh)
        g_delta[j * DHh + t] = part[0][t] + part[1][t] + part[2][t] + part[3][t];
}

// ---------------- per-token renorm + residual accumulate -----------------------
__global__ void renorm_kernel()
{
    __shared__ float red[8];
    const int j = blockIdx.x;
    const int t = threadIdx.x;   // 256 threads x 2 elems

    float y0 = g_y[(size_t)j * Dd + t];
    float y1 = g_y[(size_t)j * Dd + 256 + t];

    // reduction helper (manually unrolled 3x to keep sync structure explicit)
    float v, s;

    // m1
    v = y0 + y1;
    #pragma unroll
    for (int o = 16; o; o >>= 1) v += __shfl_xor_sync(0xffffffffu, v, o);
    if ((t & 31) == 0) red[t >> 5] = v;
    __syncthreads();
    s = 0.f;
    #pragma unroll
    for (int w = 0; w < 8; w++) s += red[w];
    __syncthreads();
    float m1 = s * (1.f / 512.f);

    y0 /= m1;
    y1 /= m1;

    // m2
    v = y0 + y1;
    #pragma unroll
    for (int o = 16; o; o >>= 1) v += __shfl_xor_sync(0xffffffffu, v, o);
    if ((t & 31) == 0) red[t >> 5] = v;
    __syncthreads();
    s = 0.f;
    #pragma unroll
    for (int w = 0; w < 8; w++) s += red[w];
    __syncthreads();
    float m2 = s * (1.f / 512.f);

    float d0 = y0 - m2, d1 = y1 - m2;

    // var (ddof=1)
    v = d0 * d0 + d1 * d1;
    #pragma unroll
    for (int o = 16; o; o >>= 1) v += __shfl_xor_sync(0xffffffffu, v, o);
    if ((t & 31) == 0) red[t >> 5] = v;
    __syncthreads();
    s = 0.f;
    #pragma unroll
    for (int w = 0; w < 8; w++) s += red[w];
    float inv_sd = rsqrtf(s * (1.f / 511.f));

    g_cur[(size_t)j * Dd + t]       += d0 * inv_sd + m2;
    g_cur[(size_t)j * Dd + 256 + t] += d1 * inv_sd + m2;
}

// ---------------- final: out = cur / H ------------------------------------------
__global__ void final_kernel(float* __restrict__ out)
{
    int i = blockIdx.x * blockDim.x + threadIdx.x;
    out[i] = g_cur[i] * (1.f / (float)Hh);
}

// ---------------- launch ---------------------------------------------------------
extern "C" void kernel_launch(void* const* d_in, const int* in_sizes, int n_in,
                              void* d_out, int out_size)
{
    const float* x   = (const float*)d_in[0];
    const float* Wq  = (const float*)d_in[1];
    const float* Wk  = (const float*)d_in[2];
    const float* Wvd = (const float*)d_in[3];
    const float* Wvu = (const float*)d_in[4];
    float* out = (float*)d_out;

    init_kernel<<<(Sq * Dd) / 256, 256>>>(x);
    for (int h = 0; h < Hh; h++) {
        qkv_gemm<<<dim3(Sq / 64, 3), 256>>>(Wq, Wk, Wvd, h);
        attn_kernel<<<Sq, 256>>>();
        up_gemm<<<dim3(Sq / 64, Dd / 64), 256>>>(Wvu, h);
        renorm_kernel<<<Sq, 256>>>();
    }
    final_kernel<<<(Sq * Dd) / 256, 256>>>(out);
}

// round 2
// speedup vs baseline: 1.2756x; 1.2756x over previous
#include <cuda_runtime.h>
#include <math.h>

#define Sq  2048
#define Dd  512
#define Hh  8
#define DHh 64
#define CWw 128
#define Ww  256   // 2*CW

// ---------------- scratch (device globals) -------------------------------------
__device__ float g_cur[Sq * Dd];
__device__ float g_q[Sq * DHh];
__device__ float g_k[Sq * DHh];
__device__ float g_v[Sq * DHh];
__device__ float g_delta[Sq * DHh];
__device__ float g_y[Sq * Dd];

// ---------------- init: cur = x -------------------------------------------------
__global__ void init_kernel(const float4* __restrict__ x) {
    int i = blockIdx.x * blockDim.x + threadIdx.x;
    ((float4*)g_cur)[i] = x[i];
}

// ---------------- GEMM body: BM x 64 tile, BK=32, [k][m] smem, vector LDS -------
// C[m,n] = sum_k A[m,k]*B[n,k]  (+ Cadd[m,n] if given)
template<int BM>
__device__ __forceinline__ void gemm_body(
    const float* __restrict__ A, int lda,
    const float* __restrict__ B, int ldb, int K,
    int m0, int n0,
    float* __restrict__ C, int ldc,
    const float* __restrict__ Cadd)
{
    constexpr int TM = BM / 16;           // 4 (BM=64) or 2 (BM=32)
    constexpr int SA = BM + 4;            // row stride (floats), mult of 4
    constexpr int SB = 68;
    __shared__ float Xs[32][SA];          // [k][m]
    __shared__ float Ws[32][SB];          // [k][n]

    const int t  = threadIdx.x;           // 256 threads
    const int tx = t & 15;                // n / 4
    const int ty = t >> 4;                // m / TM

    float acc[TM][4] = {};

    for (int k0 = 0; k0 < K; k0 += 32) {
        // load A tile (BM x 32) transposed into Xs[k][m]
        #pragma unroll
        for (int r = 0; r < BM * 8 / 256; r++) {
            int f  = t + r * 256;
            int m  = f >> 3;
            int kv = f & 7;
            float4 va = *(const float4*)&A[(size_t)(m0 + m) * lda + k0 + kv * 4];
            Xs[kv * 4 + 0][m] = va.x;
            Xs[kv * 4 + 1][m] = va.y;
            Xs[kv * 4 + 2][m] = va.z;
            Xs[kv * 4 + 3][m] = va.w;
        }
        // load B tile (64 x 32) transposed into Ws[k][n]
        #pragma unroll
        for (int r = 0; r < 2; r++) {
            int f  = t + r * 256;
            int n  = f >> 3;
            int kv = f & 7;
            float4 vb = *(const float4*)&B[(size_t)(n0 + n) * ldb + k0 + kv * 4];
            Ws[kv * 4 + 0][n] = vb.x;
            Ws[kv * 4 + 1][n] = vb.y;
            Ws[kv * 4 + 2][n] = vb.z;
            Ws[kv * 4 + 3][n] = vb.w;
        }
        __syncthreads();

        #pragma unroll
        for (int k = 0; k < 32; k++) {
            float a[TM], b[4];
            if constexpr (TM == 4) {
                float4 t4 = *(const float4*)&Xs[k][ty * 4];
                a[0] = t4.x; a[1] = t4.y; a[2] = t4.z; a[3] = t4.w;
            } else {
                float2 t2 = *(const float2*)&Xs[k][ty * 2];
                a[0] = t2.x; a[1] = t2.y;
            }
            float4 b4 = *(const float4*)&Ws[k][tx * 4];
            b[0] = b4.x; b[1] = b4.y; b[2] = b4.z; b[3] = b4.w;
            #pragma unroll
            for (int i = 0; i < TM; i++)
                #pragma unroll
                for (int j = 0; j < 4; j++)
                    acc[i][j] = fmaf(a[i], b[j], acc[i][j]);
        }
        __syncthreads();
    }

    #pragma unroll
    for (int i = 0; i < TM; i++) {
        int m = m0 + ty * TM + i;
        #pragma unroll
        for (int j = 0; j < 4; j++) {
            int n = n0 + tx * 4 + j;
            float v = acc[i][j];
            if (Cadd) v += Cadd[(size_t)m * ldc + n];
            C[(size_t)m * ldc + n] = v;
        }
    }
}

// q/k/v = cur @ W^T   grid (S/32, 3)
__global__ void qkv_gemm(const float* __restrict__ Wq,
                         const float* __restrict__ Wk,
                         const float* __restrict__ Wvd, int h)
{
    int sel = blockIdx.y;
    const float* B = (sel == 0 ? Wq : sel == 1 ? Wk : Wvd) + (size_t)h * DHh * Dd;
    float* C = (sel == 0 ? g_q : sel == 1 ? g_k : g_v);
    gemm_body<32>(g_cur, Dd, B, Dd, Dd, blockIdx.x * 32, 0, C, DHh, nullptr);
}

// y = cur + delta @ Wvu^T   grid (S/64, D/64)
__global__ void up_gemm(const float* __restrict__ Wvu, int h)
{
    gemm_body<64>(g_delta, DHh, Wvu + (size_t)h * Dd * DHh, DHh, DHh,
                  blockIdx.x * 64, blockIdx.y * 64, g_y, Dd, g_cur);
}

// ---------------- windowed attention: one block per token -----------------------
__global__ void attn_kernel()
{
    const int j = blockIdx.x;
    const int t = threadIdx.x;         // 256 threads
    __shared__ float4 qs4[16];
    __shared__ float  ws[Ww];
    __shared__ float  red[8];
    __shared__ float  part[16][64];    // 4 KB

    if (t < 16) qs4[t] = ((const float4*)&g_q[(size_t)j * DHh])[t];
    __syncthreads();

    // score for window slot t  (key index j-128+t)
    const int  iw    = j - CWw + t;
    const bool valid = (iw >= 0) && (iw < Sq);
    float s = -INFINITY;
    if (valid) {
        const float4* kr = (const float4*)&g_k[(size_t)iw * DHh];
        float acc = 0.f;
        #pragma unroll
        for (int d = 0; d < 16; d++) {
            float4 kk = kr[d];
            float4 qq = qs4[d];
            acc += kk.x * qq.x + kk.y * qq.y + kk.z * qq.z + kk.w * qq.w;
        }
        s = acc * 0.125f;
    }

    // block max
    float m = s;
    #pragma unroll
    for (int o = 16; o; o >>= 1) m = fmaxf(m, __shfl_xor_sync(0xffffffffu, m, o));
    if ((t & 31) == 0) red[t >> 5] = m;
    __syncthreads();
    m = red[0];
    #pragma unroll
    for (int w = 1; w < 8; w++) m = fmaxf(m, red[w]);
    __syncthreads();

    float e = valid ? __expf(s - m) : 0.f;

    // block sum
    float sm = e;
    #pragma unroll
    for (int o = 16; o; o >>= 1) sm += __shfl_xor_sync(0xffffffffu, sm, o);
    if ((t & 31) == 0) red[t >> 5] = sm;
    __syncthreads();
    float total = 0.f;
    #pragma unroll
    for (int w = 0; w < 8; w++) total += red[w];

    ws[t] = e / total;
    __syncthreads();

    // delta[d] = sum_w ws[w] * v[j-128+w][d]
    // 16 window groups x 16 float4 d-lanes
    const int wg = t >> 4;
    const int dv = t & 15;
    const int wlo = (CWw - j > 0) ? (CWw - j) : 0;
    int whi = Sq + CWw - j; if (whi > Ww) whi = Ww;

    float4 acc4 = make_float4(0.f, 0.f, 0.f, 0.f);
    #pragma unroll
    for (int i = 0; i < 16; i++) {
        int w = wg * 16 + i;
        if (w >= wlo && w < whi) {
            float  wt = ws[w];
            float4 vv = ((const float4*)&g_v[(size_t)(j - CWw + w) * DHh])[dv];
            acc4.x = fmaf(wt, vv.x, acc4.x);
            acc4.y = fmaf(wt, vv.y, acc4.y);
            acc4.z = fmaf(wt, vv.z, acc4.z);
            acc4.w = fmaf(wt, vv.w, acc4.w);
        }
    }
    *(float4*)&part[wg][dv * 4] = acc4;
    __syncthreads();

    if (t < DHh) {
        float sum = 0.f;
        #pragma unroll
        for (int g = 0; g < 16; g++) sum += part[g][t];
        g_delta[(size_t)j * DHh + t] = sum;
    }
}

// ---------------- per-token renorm + residual accumulate (+ final /H) ----------
__global__ void renorm_kernel(int last, float* __restrict__ out)
{
    __shared__ float red[8];
    const int j = blockIdx.x;
    const int t = threadIdx.x;   // 256 threads x 2 elems

    float y0 = g_y[(size_t)j * Dd + t];
    float y1 = g_y[(size_t)j * Dd + 256 + t];

    float v, s;

    // m1
    v = y0 + y1;
    #pragma unroll
    for (int o = 16; o; o >>= 1) v += __shfl_xor_sync(0xffffffffu, v, o);
    if ((t & 31) == 0) red[t >> 5] = v;
    __syncthreads();
    s = 0.f;
    #pragma unroll
    for (int w = 0; w < 8; w++) s += red[w];
    __syncthreads();
    float m1 = s * (1.f / 512.f);

    y0 /= m1;
    y1 /= m1;

    // m2
    v = y0 + y1;
    #pragma unroll
    for (int o = 16; o; o >>= 1) v += __shfl_xor_sync(0xffffffffu, v, o);
    if ((t & 31) == 0) red[t >> 5] = v;
    __syncthreads();
    s = 0.f;
    #pragma unroll
    for (int w = 0; w < 8; w++) s += red[w];
    __syncthreads();
    float m2 = s * (1.f / 512.f);

    float d0 = y0 - m2, d1 = y1 - m2;

    // var (ddof=1)
    v = d0 * d0 + d1 * d1;
    #pragma unroll
    for (int o = 16; o; o >>= 1) v += __shfl_xor_sync(0xffffffffu, v, o);
    if ((t & 31) == 0) red[t >> 5] = v;
    __syncthreads();
    s = 0.f;
    #pragma unroll
    for (int w = 0; w < 8; w++) s += red[w];
    float inv_sd = rsqrtf(s * (1.f / 511.f));

    float c0 = g_cur[(size_t)j * Dd + t]       + d0 * inv_sd + m2;
    float c1 = g_cur[(size_t)j * Dd + 256 + t] + d1 * inv_sd + m2;
    g_cur[(size_t)j * Dd + t]       = c0;
    g_cur[(size_t)j * Dd + 256 + t] = c1;
    if (last) {
        out[(size_t)j * Dd + t]       = c0 * (1.f / (float)Hh);
        out[(size_t)j * Dd + 256 + t] = c1 * (1.f / (float)Hh);
    }
}

// ---------------- launch ---------------------------------------------------------
extern "C" void kernel_launch(void* const* d_in, const int* in_sizes, int n_in,
                              void* d_out, int out_size)
{
    const float* x   = (const float*)d_in[0];
    const float* Wq  = (const float*)d_in[1];
    const float* Wk  = (const float*)d_in[2];
    const float* Wvd = (const float*)d_in[3];
    const float* Wvu = (const float*)d_in[4];
    float* out = (float*)d_out;

    init_kernel<<<(Sq * Dd / 4) / 256, 256>>>((const float4*)x);
    for (int h = 0; h < Hh; h++) {
        qkv_gemm<<<dim3(Sq / 32, 3), 256>>>(Wq, Wk, Wvd, h);
        attn_kernel<<<Sq, 256>>>();
        up_gemm<<<dim3(Sq / 64, Dd / 64), 256>>>(Wvu, h);
        renorm_kernel<<<Sq, 256>>>(h == Hh - 1 ? 1 : 0, out);
    }
}

// round 3
// speedup vs baseline: 2.1409x; 1.6783x over previous
#include <cuda_runtime.h>
#include <math.h>

#define Sq  2048
#define Dd  512
#define Hh  8
#define DHh 64
#define CWw 128

// ---------------- scratch (device globals) -------------------------------------
__device__ float g_cur[Sq * Dd];
__device__ float g_q[Sq * DHh];
__device__ float g_k[Sq * DHh];
__device__ float g_v[Sq * DHh];
__device__ float g_delta[Sq * DHh];

// ---------------- init: cur = x -------------------------------------------------
__global__ void init_kernel(const float4* __restrict__ x) {
    int i = blockIdx.x * blockDim.x + threadIdx.x;
    ((float4*)g_cur)[i] = x[i];
}

// ---------------- qkv GEMM: 32x64 tile, 128 threads, 4x4 microtile --------------
// C[m,n] = sum_k cur[m,k] * W[n,k]
__global__ void qkv_gemm(const float* __restrict__ Wq,
                         const float* __restrict__ Wk,
                         const float* __restrict__ Wvd, int h)
{
    __shared__ float Xs[32][36];   // [k][m]
    __shared__ float Ws[32][68];   // [k][n]

    const int sel = blockIdx.y;
    const float* B = (sel == 0 ? Wq : sel == 1 ? Wk : Wvd) + (size_t)h * DHh * Dd;
    float* C = (sel == 0 ? g_q : sel == 1 ? g_k : g_v);
    const int m0 = blockIdx.x * 32;

    const int t  = threadIdx.x;    // 128
    const int tx = t & 15;         // n4
    const int ty = t >> 4;         // 0..7 -> m base ty*4

    float acc[4][4] = {};

    for (int k0 = 0; k0 < Dd; k0 += 32) {
        #pragma unroll
        for (int r = 0; r < 2; r++) {
            int f = t + r * 128;
            int m = f >> 3, kv = f & 7;
            float4 va = *(const float4*)&g_cur[(size_t)(m0 + m) * Dd + k0 + kv * 4];
            Xs[kv * 4 + 0][m] = va.x;
            Xs[kv * 4 + 1][m] = va.y;
            Xs[kv * 4 + 2][m] = va.z;
            Xs[kv * 4 + 3][m] = va.w;
        }
        #pragma unroll
        for (int r = 0; r < 4; r++) {
            int f = t + r * 128;
            int n = f >> 3, kv = f & 7;
            float4 vb = *(const float4*)&B[(size_t)n * Dd + k0 + kv * 4];
            Ws[kv * 4 + 0][n] = vb.x;
            Ws[kv * 4 + 1][n] = vb.y;
            Ws[kv * 4 + 2][n] = vb.z;
            Ws[kv * 4 + 3][n] = vb.w;
        }
        __syncthreads();

        #pragma unroll
        for (int k = 0; k < 32; k++) {
            float4 a4 = *(const float4*)&Xs[k][ty * 4];
            float4 b4 = *(const float4*)&Ws[k][tx * 4];
            float a[4] = {a4.x, a4.y, a4.z, a4.w};
            float b[4] = {b4.x, b4.y, b4.z, b4.w};
            #pragma unroll
            for (int i = 0; i < 4; i++)
                #pragma unroll
                for (int j = 0; j < 4; j++)
                    acc[i][j] = fmaf(a[i], b[j], acc[i][j]);
        }
        __syncthreads();
    }

    #pragma unroll
    for (int i = 0; i < 4; i++) {
        float4 o = make_float4(acc[i][0], acc[i][1], acc[i][2], acc[i][3]);
        *(float4*)&C[(size_t)(m0 + ty * 4 + i) * DHh + tx * 4] = o;
    }
}

// ---------------- flash-style windowed attention --------------------------------
// block = 16 queries; keys staged in smem for range [j0-128, j0+160)
#define KEXT 288
#define KP   68     // row pitch (floats) for K/V tiles
#define PP   292    // row pitch for P

__global__ void attn_flash()
{
    extern __shared__ float sm[];
    float* Ks = sm;                         // [288][68]
    float* Vs = sm + KEXT * KP;             // [288][68]
    float* Ps = sm + 2 * KEXT * KP;         // [16][292]
    float* Qs = Ps + 16 * PP;               // [16][64]
    float* Rs = sm;                         // partials, reuse Ks region (8192 floats)

    const int t  = threadIdx.x;             // 256
    const int j0 = blockIdx.x * 16;
    const int kb = j0 - CWw;

    // load K/V window (zero-fill out-of-range rows)
    for (int f = t; f < KEXT * 16; f += 256) {
        int kk = f >> 4, d4 = f & 15;
        int gk = kb + kk;
        float4 kv = make_float4(0.f, 0.f, 0.f, 0.f);
        float4 vv = kv;
        if (gk >= 0 && gk < Sq) {
            kv = ((const float4*)&g_k[(size_t)gk * DHh])[d4];
            vv = ((const float4*)&g_v[(size_t)gk * DHh])[d4];
        }
        *(float4*)&Ks[kk * KP + d4 * 4] = kv;
        *(float4*)&Vs[kk * KP + d4 * 4] = vv;
    }
    { // load Q tile
        int q = t >> 4, d4 = t & 15;
        ((float4*)&Qs[q * DHh])[d4] = ((const float4*)&g_q[(size_t)(j0 + q) * DHh])[d4];
    }
    __syncthreads();

    const int w    = t >> 5;
    const int lane = t & 31;

    // ---- scores: warp w owns queries q0=2w, q1=2w+1; lane owns kk = lane+32*jj
    const int q0 = 2 * w, q1 = 2 * w + 1;
    float a0[9] = {}, a1[9] = {};
    #pragma unroll
    for (int d4 = 0; d4 < 16; d4++) {
        float4 qa = *(const float4*)&Qs[q0 * DHh + d4 * 4];
        float4 qb = *(const float4*)&Qs[q1 * DHh + d4 * 4];
        #pragma unroll
        for (int jj = 0; jj < 9; jj++) {
            const float4 kv = *(const float4*)&Ks[(lane + 32 * jj) * KP + d4 * 4];
            a0[jj] = fmaf(kv.x, qa.x, fmaf(kv.y, qa.y, fmaf(kv.z, qa.z, fmaf(kv.w, qa.w, a0[jj]))));
            a1[jj] = fmaf(kv.x, qb.x, fmaf(kv.y, qb.y, fmaf(kv.z, qb.z, fmaf(kv.w, qb.w, a1[jj]))));
        }
    }

    // mask + scale
    float m0 = -1e30f, m1 = -1e30f;
    #pragma unroll
    for (int jj = 0; jj < 9; jj++) {
        int kk = lane + 32 * jj;
        int gk = kb + kk;
        bool gok = (gk >= 0) && (gk < Sq);
        bool v0 = gok && (kk >= q0) && (kk < q0 + 256);
        bool v1 = gok && (kk >= q1) && (kk < q1 + 256);
        a0[jj] = v0 ? a0[jj] * 0.125f : -1e30f;
        a1[jj] = v1 ? a1[jj] * 0.125f : -1e30f;
        m0 = fmaxf(m0, a0[jj]);
        m1 = fmaxf(m1, a1[jj]);
    }
    #pragma unroll
    for (int o = 16; o; o >>= 1) {
        m0 = fmaxf(m0, __shfl_xor_sync(0xffffffffu, m0, o));
        m1 = fmaxf(m1, __shfl_xor_sync(0xffffffffu, m1, o));
    }
    float s0 = 0.f, s1 = 0.f;
    #pragma unroll
    for (int jj = 0; jj < 9; jj++) {
        a0[jj] = __expf(a0[jj] - m0);
        a1[jj] = __expf(a1[jj] - m1);
        s0 += a0[jj];
        s1 += a1[jj];
    }
    #pragma unroll
    for (int o = 16; o; o >>= 1) {
        s0 += __shfl_xor_sync(0xffffffffu, s0, o);
        s1 += __shfl_xor_sync(0xffffffffu, s1, o);
    }
    const float i0 = 1.f / s0, i1 = 1.f / s1;
    #pragma unroll
    for (int jj = 0; jj < 9; jj++) {
        Ps[q0 * PP + lane + 32 * jj] = a0[jj] * i0;
        Ps[q1 * PP + lane + 32 * jj] = a1[jj] * i1;
    }
    __syncthreads();

    // ---- AV: warp w owns keys [36w, 36w+36); lane: qh=lane>>4 (8 queries), d4=lane&15
    const int qh = (lane >> 4) * 8;
    const int d4 = lane & 15;
    float4 r[8] = {};
    for (int i = 0; i < 36; i++) {
        int kk = w * 36 + i;
        float4 v4 = *(const float4*)&Vs[kk * KP + d4 * 4];
        #pragma unroll
        for (int qi = 0; qi < 8; qi++) {
            float p = Ps[(qh + qi) * PP + kk];
            r[qi].x = fmaf(p, v4.x, r[qi].x);
            r[qi].y = fmaf(p, v4.y, r[qi].y);
            r[qi].z = fmaf(p, v4.z, r[qi].z);
            r[qi].w = fmaf(p, v4.w, r[qi].w);
        }
    }
    #pragma unroll
    for (int qi = 0; qi < 8; qi++)
        *(float4*)&Rs[(w * 16 + qh + qi) * DHh + d4 * 4] = r[qi];
    __syncthreads();

    // reduce 8 warp-partials -> g_delta
    #pragma unroll
    for (int ii = 0; ii < 4; ii++) {
        int idx = t + 256 * ii;          // 0..1023
        int q = idx >> 6, d = idx & 63;
        float s = 0.f;
        #pragma unroll
        for (int ww = 0; ww < 8; ww++) s += Rs[(ww * 16 + q) * DHh + d];
        g_delta[(size_t)(j0 + q) * DHh + d] = s;
    }
}

// ---------------- fused up-projection + residual + renorm -----------------------
// block = 16 tokens; full Wvu head slice staged in smem [k][n], pitch 516
#define WP 516

__global__ void upnorm_kernel(const float* __restrict__ Wvu, int h,
                              int last, float* __restrict__ out)
{
    extern __shared__ float sm[];
    float* Ws = sm;                 // [64][516]
    float* As = sm + 64 * WP;       // [16][64] delta tile

    const int t  = threadIdx.x;     // 256
    const int m0 = blockIdx.x * 16;
    const float* W = Wvu + (size_t)h * Dd * DHh;

    { // load + transpose Wvu: lanes 0..15 share k4 (conflict-free STS)
        int k4 = t >> 4;            // 0..15
        int nb = t & 15;
        for (int i = 0; i < 32; i++) {
            int n = nb + 16 * i;
            float4 wv = *(const float4*)&W[(size_t)n * DHh + k4 * 4];
            Ws[(4 * k4 + 0) * WP + n] = wv.x;
            Ws[(4 * k4 + 1) * WP + n] = wv.y;
            Ws[(4 * k4 + 2) * WP + n] = wv.z;
            Ws[(4 * k4 + 3) * WP + n] = wv.w;
        }
    }
    { // load delta tile
        int m = t >> 4, k4 = t & 15;
        ((float4*)&As[m * DHh])[k4] = ((const float4*)&g_delta[(size_t)(m0 + m) * DHh])[k4];
    }
    __syncthreads();

    const int w    = t >> 5;
    const int lane = t & 31;
    const int r0 = m0 + 2 * w, r1 = r0 + 1;

    float4 y0[4] = {}, y1[4] = {};
    for (int k = 0; k < DHh; k++) {
        float av0 = As[(2 * w) * DHh + k];
        float av1 = As[(2 * w + 1) * DHh + k];
        #pragma unroll
        for (int j = 0; j < 4; j++) {
            float4 wv = *(const float4*)&Ws[k * WP + 4 * (lane + 32 * j)];
            y0[j].x = fmaf(av0, wv.x, y0[j].x);
            y0[j].y = fmaf(av0, wv.y, y0[j].y);
            y0[j].z = fmaf(av0, wv.z, y0[j].z);
            y0[j].w = fmaf(av0, wv.w, y0[j].w);
            y1[j].x = fmaf(av1, wv.x, y1[j].x);
            y1[j].y = fmaf(av1, wv.y, y1[j].y);
            y1[j].z = fmaf(av1, wv.z, y1[j].z);
            y1[j].w = fmaf(av1, wv.w, y1[j].w);
        }
    }

    // add residual (keep cur for final accumulate)
    float4 c0[4], c1[4];
    #pragma unroll
    for (int j = 0; j < 4; j++) {
        c0[j] = ((const float4*)&g_cur[(size_t)r0 * Dd])[lane + 32 * j];
        c1[j] = ((const float4*)&g_cur[(size_t)r1 * Dd])[lane + 32 * j];
        y0[j].x += c0[j].x; y0[j].y += c0[j].y; y0[j].z += c0[j].z; y0[j].w += c0[j].w;
        y1[j].x += c1[j].x; y1[j].y += c1[j].y; y1[j].z += c1[j].z; y1[j].w += c1[j].w;
    }

    // renorm row r0 and r1 (warp-local)
    float t0 = 0.f, t1 = 0.f;
    #pragma unroll
    for (int j = 0; j < 4; j++) {
        t0 += y0[j].x + y0[j].y + y0[j].z + y0[j].w;
        t1 += y1[j].x + y1[j].y + y1[j].z + y1[j].w;
    }
    #pragma unroll
    for (int o = 16; o; o >>= 1) {
        t0 += __shfl_xor_sync(0xffffffffu, t0, o);
        t1 += __shfl_xor_sync(0xffffffffu, t1, o);
    }
    float im0 = 512.f / t0, im1 = 512.f / t1;   // 1/m1
    #pragma unroll
    for (int j = 0; j < 4; j++) {
        y0[j].x *= im0; y0[j].y *= im0; y0[j].z *= im0; y0[j].w *= im0;
        y1[j].x *= im1; y1[j].y *= im1; y1[j].z *= im1; y1[j].w *= im1;
    }
    t0 = 0.f; t1 = 0.f;
    #pragma unroll
    for (int j = 0; j < 4; j++) {
        t0 += y0[j].x + y0[j].y + y0[j].z + y0[j].w;
        t1 += y1[j].x + y1[j].y + y1[j].z + y1[j].w;
    }
    #pragma unroll
    for (int o = 16; o; o >>= 1) {
        t0 += __shfl_xor_sync(0xffffffffu, t0, o);
        t1 += __shfl_xor_sync(0xffffffffu, t1, o);
    }
    float mu0 = t0 * (1.f / 512.f), mu1 = t1 * (1.f / 512.f);
    float v0 = 0.f, v1 = 0.f;
    #pragma unroll
    for (int j = 0; j < 4; j++) {
        y0[j].x -= mu0; y0[j].y -= mu0; y0[j].z -= mu0; y0[j].w -= mu0;
        y1[j].x -= mu1; y1[j].y -= mu1; y1[j].z -= mu1; y1[j].w -= mu1;
        v0 += y0[j].x*y0[j].x + y0[j].y*y0[j].y + y0[j].z*y0[j].z + y0[j].w*y0[j].w;
        v1 += y1[j].x*y1[j].x + y1[j].y*y1[j].y + y1[j].z*y1[j].z + y1[j].w*y1[j].w;
    }
    #pragma unroll
    for (int o = 16; o; o >>= 1) {
        v0 += __shfl_xor_sync(0xffffffffu, v0, o);
        v1 += __shfl_xor_sync(0xffffffffu, v1, o);
    }
    float is0 = rsqrtf(v0 * (1.f / 511.f));
    float is1 = rsqrtf(v1 * (1.f / 511.f));

    #pragma unroll
    for (int j = 0; j < 4; j++) {
        float4 n0, n1;
        n0.x = c0[j].x + y0[j].x * is0 + mu0;
        n0.y = c0[j].y + y0[j].y * is0 + mu0;
        n0.z = c0[j].z + y0[j].z * is0 + mu0;
        n0.w = c0[j].w + y0[j].w * is0 + mu0;
        n1.x = c1[j].x + y1[j].x * is1 + mu1;
        n1.y = c1[j].y + y1[j].y * is1 + mu1;
        n1.z = c1[j].z + y1[j].z * is1 + mu1;
        n1.w = c1[j].w + y1[j].w * is1 + mu1;
        ((float4*)&g_cur[(size_t)r0 * Dd])[lane + 32 * j] = n0;
        ((float4*)&g_cur[(size_t)r1 * Dd])[lane + 32 * j] = n1;
        if (last) {
            n0.x *= 0.125f; n0.y *= 0.125f; n0.z *= 0.125f; n0.w *= 0.125f;
            n1.x *= 0.125f; n1.y *= 0.125f; n1.z *= 0.125f; n1.w *= 0.125f;
            ((float4*)&out[(size_t)r0 * Dd])[lane + 32 * j] = n0;
            ((float4*)&out[(size_t)r1 * Dd])[lane + 32 * j] = n1;
        }
    }
}

// ---------------- launch ---------------------------------------------------------
extern "C" void kernel_launch(void* const* d_in, const int* in_sizes, int n_in,
                              void* d_out, int out_size)
{
    const float* x   = (const float*)d_in[0];
    const float* Wq  = (const float*)d_in[1];
    const float* Wk  = (const float*)d_in[2];
    const float* Wvd = (const float*)d_in[3];
    const float* Wvu = (const float*)d_in[4];
    float* out = (float*)d_out;

    const int attn_smem = (2 * KEXT * KP + 16 * PP + 16 * DHh) * 4;   // 179456
    const int up_smem   = (64 * WP + 16 * DHh) * 4;                   // 136192
    cudaFuncSetAttribute(attn_flash, cudaFuncAttributeMaxDynamicSharedMemorySize, attn_smem);
    cudaFuncSetAttribute(upnorm_kernel, cudaFuncAttributeMaxDynamicSharedMemorySize, up_smem);

    init_kernel<<<(Sq * Dd / 4) / 256, 256>>>((const float4*)x);
    for (int h = 0; h < Hh; h++) {
        qkv_gemm<<<dim3(Sq / 32, 3), 128>>>(Wq, Wk, Wvd, h);
        attn_flash<<<Sq / 16, 256, attn_smem>>>();
        upnorm_kernel<<<Sq / 16, 256, up_smem>>>(Wvu, h, h == Hh - 1 ? 1 : 0, out);
    }
}